// round 6
// baseline (speedup 1.0000x reference)
#include <cuda_runtime.h>
#include <cstdint>

#define EDIM 256
#define NE 1024
#define HW 4096
#define N_TOK 65536
#define ZQ_ELEMS 16777216
#define OFF_LOSS 16777216
#define OFF_ZERO 16777217
#define OFF_IDX  16777218

typedef unsigned long long ull;

__device__ int   g_idx[N_TOK];
__device__ float g_cnorm[NE];
__device__ float g_part[16384];

__device__ __forceinline__ ull pk(float a, float b){
    ull r; asm("mov.b64 %0, {%1,%2};" : "=l"(r) : "f"(a), "f"(b)); return r;
}
__device__ __forceinline__ void fma2(ull& d, ull a, ull b){
    asm("fma.rn.f32x2 %0, %1, %2, %0;" : "+l"(d) : "l"(a), "l"(b));
}
__device__ __forceinline__ void unpk(ull v, float& a, float& b){
    asm("mov.b64 {%0,%1}, %2;" : "=f"(a), "=f"(b) : "l"(v));
}
// monotone float->uint map: order-preserving for all finite floats
__device__ __forceinline__ unsigned fenc(float x){
    unsigned u = __float_as_uint(x);
    return (u & 0x80000000u) ? ~u : (u | 0x80000000u);
}

// -------------------- kernel 1: codebook squared norms --------------------
__global__ void cnorm_kernel(const float* __restrict__ cb){
    __shared__ float red[256];
    int tid = threadIdx.x;
    float v = cb[blockIdx.x * EDIM + tid];
    red[tid] = v * v;
    __syncthreads();
    for (int s = 128; s > 0; s >>= 1){
        if (tid < s) red[tid] += red[tid + s];
        __syncthreads();
    }
    if (tid == 0) g_cnorm[blockIdx.x] = red[0];
}

// -------------------- kernel 2: fused distance GEMM + argmin --------------------
// Block: 64 tokens x all 1024 codes (4 tiles of 256). 256 threads, each 8 tok x 8 codes.
// score = ||c||^2 - 2*dot(z,c)   (||z||^2 constant per token -> argmin-invariant)
// Inner loop: all operands arrive as native f32x2 register pairs from LDS.128.
//   z  smem: [256 k][64 tok]              -> ulonglong2 loads give token-pair packs
//   cb smem: [2 buf][8 k][256 codes x2]   -> each value pre-DUPLICATED (broadcast pack)
// Double-buffered c-tile: one __syncthreads per 8-k chunk, LDG prefetched a full
// compute phase ahead.
__global__ __launch_bounds__(256, 2)
void vq_argmin_kernel(const float* __restrict__ z, const float* __restrict__ cb,
                      float* __restrict__ out){
    extern __shared__ char smem_raw[];
    float* zs   = (float*)smem_raw;                       // 65536 B
    float* cs   = (float*)(smem_raw + 65536);             // 2*8*512 floats = 32768 B
    ull*   keys = (ull*)(smem_raw + 65536 + 32768);       // 64 * 8 B

    const int tid = threadIdx.x;
    const int n0  = blockIdx.x << 6;
    const int b   = n0 >> 12;
    const int hw0 = n0 & 4095;
    const float* zbase = z + (size_t)b * (EDIM * HW) + hw0;

    // Load z tile [256 k][64 tok], coalesced float4 over tokens
    for (int i = tid; i < 4096; i += 256){
        int k  = i >> 4;
        int t4 = (i & 15) << 2;
        float4 v = *(const float4*)(zbase + (size_t)k * HW + t4);
        *(float4*)(zs + k * 64 + t4) = v;
    }
    if (tid < 64) keys[tid] = ~0ULL;

    const int tt   = tid & 7;         // token group
    const int tc   = tid >> 3;        // code group within 256-code tile
    const int tok0 = tt << 3;

    for (int tile = 0; tile < 4; tile++){
        const int cbase = tile << 8;
        const float* crow = cb + (size_t)(cbase + tid) * EDIM;

        ull acc[4][8];
        #pragma unroll
        for (int tp = 0; tp < 4; tp++)
            #pragma unroll
            for (int j = 0; j < 8; j++) acc[tp][j] = 0ULL;

        // prologue: fetch chunk 0 (8 k values of this thread's code row)
        float4 p0 = __ldg((const float4*)crow);
        float4 p1 = __ldg((const float4*)(crow + 4));

        __syncthreads();   // tile 0: z tile ready; tiles >0: prev chunk reads done

        // store chunk 0 duplicated into buf 0
        {
            float* dst = cs + (tid << 1);
            *(ull*)(dst + 0*512) = pk(p0.x, p0.x);
            *(ull*)(dst + 1*512) = pk(p0.y, p0.y);
            *(ull*)(dst + 2*512) = pk(p0.z, p0.z);
            *(ull*)(dst + 3*512) = pk(p0.w, p0.w);
            *(ull*)(dst + 4*512) = pk(p1.x, p1.x);
            *(ull*)(dst + 5*512) = pk(p1.y, p1.y);
            *(ull*)(dst + 6*512) = pk(p1.z, p1.z);
            *(ull*)(dst + 7*512) = pk(p1.w, p1.w);
        }

        for (int ch = 0; ch < 32; ch++){
            const int buf = ch & 1;
            // prefetch next chunk (overlaps barrier + this chunk's compute)
            if (ch < 31){
                p0 = __ldg((const float4*)(crow + ((ch + 1) << 3)));
                p1 = __ldg((const float4*)(crow + ((ch + 1) << 3) + 4));
            }
            __syncthreads();   // chunk ch's STS visible to all

            const float* cbuf = cs + (buf << 12);
            #pragma unroll
            for (int k = 0; k < 8; k++){
                const ulonglong2* zr =
                    (const ulonglong2*)(zs + (((ch << 3) + k) << 6) + tok0);
                ulonglong2 za = zr[0];
                ulonglong2 zb = zr[1];
                const ulonglong2* cr =
                    (const ulonglong2*)(cbuf + (k << 9) + (tc << 4));
                ulonglong2 ca = cr[0], c2 = cr[1], c4 = cr[2], c6 = cr[3];

                fma2(acc[0][0], za.x, ca.x); fma2(acc[1][0], za.y, ca.x);
                fma2(acc[2][0], zb.x, ca.x); fma2(acc[3][0], zb.y, ca.x);
                fma2(acc[0][1], za.x, ca.y); fma2(acc[1][1], za.y, ca.y);
                fma2(acc[2][1], zb.x, ca.y); fma2(acc[3][1], zb.y, ca.y);
                fma2(acc[0][2], za.x, c2.x); fma2(acc[1][2], za.y, c2.x);
                fma2(acc[2][2], zb.x, c2.x); fma2(acc[3][2], zb.y, c2.x);
                fma2(acc[0][3], za.x, c2.y); fma2(acc[1][3], za.y, c2.y);
                fma2(acc[2][3], zb.x, c2.y); fma2(acc[3][3], zb.y, c2.y);
                fma2(acc[0][4], za.x, c4.x); fma2(acc[1][4], za.y, c4.x);
                fma2(acc[2][4], zb.x, c4.x); fma2(acc[3][4], zb.y, c4.x);
                fma2(acc[0][5], za.x, c4.y); fma2(acc[1][5], za.y, c4.y);
                fma2(acc[2][5], zb.x, c4.y); fma2(acc[3][5], zb.y, c4.y);
                fma2(acc[0][6], za.x, c6.x); fma2(acc[1][6], za.y, c6.x);
                fma2(acc[2][6], zb.x, c6.x); fma2(acc[3][6], zb.y, c6.x);
                fma2(acc[0][7], za.x, c6.y); fma2(acc[1][7], za.y, c6.y);
                fma2(acc[2][7], zb.x, c6.y); fma2(acc[3][7], zb.y, c6.y);
            }

            // store next chunk into the other buffer (its previous contents were
            // consumed in chunk ch-1, which all warps finished before this
            // iteration's __syncthreads)
            if (ch < 31){
                float* dst = cs + ((buf ^ 1) << 12) + (tid << 1);
                *(ull*)(dst + 0*512) = pk(p0.x, p0.x);
                *(ull*)(dst + 1*512) = pk(p0.y, p0.y);
                *(ull*)(dst + 2*512) = pk(p0.z, p0.z);
                *(ull*)(dst + 3*512) = pk(p0.w, p0.w);
                *(ull*)(dst + 4*512) = pk(p1.x, p1.x);
                *(ull*)(dst + 5*512) = pk(p1.y, p1.y);
                *(ull*)(dst + 6*512) = pk(p1.z, p1.z);
                *(ull*)(dst + 7*512) = pk(p1.w, p1.w);
            }
        }

        // tile epilogue: per-token register pre-min over this thread's 8 codes,
        // then one smem atomicMin per token
        ull tb[8];
        #pragma unroll
        for (int i = 0; i < 8; i++) tb[i] = ~0ULL;
        #pragma unroll
        for (int j = 0; j < 8; j++){
            int code = cbase + (tc << 3) + j;
            float cn = g_cnorm[code];
            #pragma unroll
            for (int tp = 0; tp < 4; tp++){
                float d0, d1;
                unpk(acc[tp][j], d0, d1);
                ull k0 = ((ull)fenc(cn - 2.0f * d0) << 32) | (unsigned)code;
                ull k1 = ((ull)fenc(cn - 2.0f * d1) << 32) | (unsigned)code;
                if (k0 < tb[2*tp])     tb[2*tp]     = k0;
                if (k1 < tb[2*tp + 1]) tb[2*tp + 1] = k1;
            }
        }
        #pragma unroll
        for (int i = 0; i < 8; i++) atomicMin(&keys[tok0 + i], tb[i]);
    }

    __syncthreads();
    if (tid < 64){
        int idx = (int)(unsigned)(keys[tid] & 0xFFFFFFFFULL);
        g_idx[n0 + tid] = idx;
        out[OFF_IDX + n0 + tid] = (float)idx;
    }
}

// -------------------- kernel 3: gather z_q (B,C,H,W) + loss partials --------------------
__global__ void gather_kernel(const float* __restrict__ z, const float* __restrict__ cb,
                              float* __restrict__ out){
    __shared__ float red[8];
    int t  = blockIdx.x * 256 + threadIdx.x;
    int o4 = t << 2;
    int b   = o4 >> 20;
    int rem = o4 & 1048575;
    int c   = rem >> 12;
    int hw  = rem & 4095;
    int n   = (b << 12) + hw;

    float4 zv = *(const float4*)(z + o4);
    int i0 = g_idx[n], i1 = g_idx[n+1], i2 = g_idx[n+2], i3 = g_idx[n+3];
    float4 q;
    q.x = __ldg(cb + (size_t)i0 * EDIM + c);
    q.y = __ldg(cb + (size_t)i1 * EDIM + c);
    q.z = __ldg(cb + (size_t)i2 * EDIM + c);
    q.w = __ldg(cb + (size_t)i3 * EDIM + c);
    *(float4*)(out + o4) = q;

    float dx = q.x - zv.x, dy = q.y - zv.y, dz = q.z - zv.z, dw = q.w - zv.w;
    float s = dx*dx + dy*dy + dz*dz + dw*dw;

    #pragma unroll
    for (int off = 16; off; off >>= 1) s += __shfl_down_sync(0xffffffffu, s, off);
    int lane = threadIdx.x & 31, wid = threadIdx.x >> 5;
    if (lane == 0) red[wid] = s;
    __syncthreads();
    if (wid == 0){
        float v = (lane < 8) ? red[lane] : 0.0f;
        #pragma unroll
        for (int off = 4; off; off >>= 1) v += __shfl_down_sync(0xffffffffu, v, off);
        if (lane == 0) g_part[blockIdx.x] = v;
    }
}

// -------------------- kernel 4: deterministic final loss reduction --------------------
__global__ void finalize_kernel(float* __restrict__ out){
    __shared__ float red[256];
    int tid = threadIdx.x;
    float s = 0.0f;
    for (int j = 0; j < 64; j++) s += g_part[tid + (j << 8)];
    red[tid] = s;
    __syncthreads();
    for (int st = 128; st > 0; st >>= 1){
        if (tid < st) red[tid] += red[tid + st];
        __syncthreads();
    }
    if (tid == 0){
        out[OFF_LOSS] = red[0] / 16777216.0f;
        out[OFF_ZERO] = 0.0f;
    }
}

// -------------------- launch --------------------
extern "C" void kernel_launch(void* const* d_in, const int* in_sizes, int n_in,
                              void* d_out, int out_size){
    const float* z  = (const float*)d_in[0];
    const float* cb = (const float*)d_in[1];
    if (n_in >= 2 && in_sizes[0] == NE * EDIM && in_sizes[1] == ZQ_ELEMS){
        const float* t = z; z = cb; cb = t;
    }
    float* out = (float*)d_out;

    const int SMEM = 65536 + 32768 + 512;   // zs + cs(dup,2buf) + keys = 98816 B
    cudaFuncSetAttribute(vq_argmin_kernel,
                         cudaFuncAttributeMaxDynamicSharedMemorySize, SMEM);

    cnorm_kernel<<<NE, 256>>>(cb);
    vq_argmin_kernel<<<N_TOK / 64, 256, SMEM>>>(z, cb, out);
    gather_kernel<<<ZQ_ELEMS / 1024, 256>>>(z, cb, out);
    finalize_kernel<<<1, 256>>>(out);
}